// round 10
// baseline (speedup 1.0000x reference)
#include <cuda_runtime.h>
#include <cuda_bf16.h>
#include <cstdint>

#define CORES   512
#define SLOTS   4
#define SLEN    64
#define PER_CORE (SLOTS * SLEN)          // 256
#define NSLOTS  (CORES * SLOTS)          // 2048 slots per layer
#define VEC_N   (CORES * PER_CORE)       // 131072
#define C_ENTRIES (CORES * SLOTS * CORES * SLOTS)
#define LIST_CAP 4                       // each slot has <=4 sources
#define GRID_MV 444                      // 148 SMs x 3 CTAs (one exact wave)
#define MV_TASKS8 (VEC_N / 8)            // 16384 8-row warp tasks
#define GW_STRIDE (GRID_MV * 8)          // 3552 warps

// Scratch packed so one memset node clears counters + list padding.
struct Scratch {
    int  cnt[2 * NSLOTS];
    int2 lst[2 * NSLOTS * LIST_CAP];     // zero entry = (src 0, weight 0.0f)
};
__device__ Scratch g_s;
__device__ float g_y1[VEC_N];

// ---------------------------------------------------------------------------
// Compact both routing tensors in one launch.
// C layout [I,J,K,L]: q = ij*512 + k indexes a float4 over l.
// ---------------------------------------------------------------------------
__global__ void compact_kernel(const float4* __restrict__ C1,
                               const float4* __restrict__ C2,
                               int* __restrict__ cnt,
                               int2* __restrict__ lst) {
    const int n4 = C_ENTRIES / 4;           // per tensor
    int g = blockIdx.x * blockDim.x + threadIdx.x;
    int half = gridDim.x * blockDim.x / 2;
    const float4* C = (g < half) ? C1 : C2;
    int* cn  = (g < half) ? cnt : cnt + NSLOTS;
    int2* ls = (g < half) ? lst : lst + NSLOTS * LIST_CAP;
    int base = (g < half) ? g : g - half;
    int stride = half;
    for (int q = base; q < n4; q += stride) {
        float4 v = __ldcs(&C[q]);
        int ij = q >> 9;
        int k  = q & 511;
        float vals[4] = {v.x, v.y, v.z, v.w};
#pragma unroll
        for (int l = 0; l < 4; l++) {
            if (vals[l] != 0.0f) {
                int s = k * 4 + l;
                int pos = atomicAdd(&cn[s], 1);
                if (pos < LIST_CAP)
                    ls[s * LIST_CAP + pos] = make_int2(ij, __float_as_int(vals[l]));
            }
        }
    }
}

// ---------------------------------------------------------------------------
// Fused dispatch + streaming matvec + capped ReLU, barrier-free.
// Task t (8 rows): core = t>>5, rows (t&31)*8 + {sub, sub+4}.
// Inline gather: h4 chunk for (lg, tt) lives at slot a = tt>>1 of this core,
// m4 = lg + 8*(tt&1). Slot lists (2 int4 each, L1-broadcast) + 4 src float4
// per chunk (L1/L2-hot; src0/w0.0f padding safe). Then 16 streaming W LDG.128
// (two rows per lane), 2 acc chains, interleaved 3-level shfl reduce.
// W per-core layout [j,k,l,m]: row r=(j,l) stride j:16384 l:64; col c=(k,m).
// ---------------------------------------------------------------------------
__global__ void __launch_bounds__(256, 3) mv_kernel(
        const float* __restrict__ W,
        const int4* __restrict__ lst4,     // 8 int4 per core (4 slots x 4 entries)
        const float4* __restrict__ src4,   // layer input, float4 view
        float* __restrict__ y) {
    const int warp = threadIdx.x >> 5, lane = threadIdx.x & 31;
    const int lg  = lane & 7;
    const int sub = lane >> 3;
    const int gw  = blockIdx.x * 8 + warp;

    for (int t = gw; t < MV_TASKS8; t += GW_STRIDE) {
        const int core = t >> 5;
        const int rg   = t & 31;
        const int r0 = (rg << 3) + sub;       // rows r0 and r0+4
        const int r1 = r0 + 4;

        // --- inline gather of this lane's 8 h chunks ---
        const int4* lb = lst4 + (core << 3);
        float4 hv[8];
#pragma unroll
        for (int a = 0; a < 4; a++) {
            int4 e01 = lb[2 * a];
            int4 e23 = lb[2 * a + 1];
            float w0 = __int_as_float(e01.y), w1 = __int_as_float(e01.w);
            float w2 = __int_as_float(e23.y), w3 = __int_as_float(e23.w);
            const int b0 = e01.x * 16, b1 = e01.z * 16;
            const int b2 = e23.x * 16, b3 = e23.z * 16;
            {
                const int m4 = lg;
                float4 v0 = src4[b0 + m4], v1 = src4[b1 + m4];
                float4 v2 = src4[b2 + m4], v3 = src4[b3 + m4];
                float4 r;
                r.x = w0 * v0.x + w1 * v1.x + w2 * v2.x + w3 * v3.x;
                r.y = w0 * v0.y + w1 * v1.y + w2 * v2.y + w3 * v3.y;
                r.z = w0 * v0.z + w1 * v1.z + w2 * v2.z + w3 * v3.z;
                r.w = w0 * v0.w + w1 * v1.w + w2 * v2.w + w3 * v3.w;
                hv[2 * a] = r;
            }
            {
                const int m4 = lg + 8;
                float4 v0 = src4[b0 + m4], v1 = src4[b1 + m4];
                float4 v2 = src4[b2 + m4], v3 = src4[b3 + m4];
                float4 r;
                r.x = w0 * v0.x + w1 * v1.x + w2 * v2.x + w3 * v3.x;
                r.y = w0 * v0.y + w1 * v1.y + w2 * v2.y + w3 * v3.y;
                r.z = w0 * v0.z + w1 * v1.z + w2 * v2.z + w3 * v3.z;
                r.w = w0 * v0.w + w1 * v1.w + w2 * v2.w + w3 * v3.w;
                hv[2 * a + 1] = r;
            }
        }

        // --- streaming W reads + dual accumulation ---
        const float* Wc = W + ((size_t)core << 16);
        const float* rb0 = Wc + ((r0 >> 6) << 14) + ((r0 & 63) << 6);
        const float* rb1 = Wc + ((r1 >> 6) << 14) + ((r1 & 63) << 6);

        float a0 = 0.f, a1 = 0.f;
#pragma unroll
        for (int tt = 0; tt < 8; tt++) {
            const int c = 4 * lg + 32 * tt;
            const int off = ((c >> 6) << 12) + (c & 63);
            float4 w0 = __ldcs(reinterpret_cast<const float4*>(rb0 + off));
            float4 w1 = __ldcs(reinterpret_cast<const float4*>(rb1 + off));
            a0 += w0.x * hv[tt].x + w0.y * hv[tt].y + w0.z * hv[tt].z + w0.w * hv[tt].w;
            a1 += w1.x * hv[tt].x + w1.y * hv[tt].y + w1.z * hv[tt].z + w1.w * hv[tt].w;
        }
        a0 += __shfl_xor_sync(0xffffffffu, a0, 1);
        a1 += __shfl_xor_sync(0xffffffffu, a1, 1);
        a0 += __shfl_xor_sync(0xffffffffu, a0, 2);
        a1 += __shfl_xor_sync(0xffffffffu, a1, 2);
        a0 += __shfl_xor_sync(0xffffffffu, a0, 4);
        a1 += __shfl_xor_sync(0xffffffffu, a1, 4);
        if (lg == 0) {
            y[(core << 8) + r0] = fminf(fmaxf(a0, 0.0f), 10.0f);
            y[(core << 8) + r1] = fminf(fmaxf(a1, 0.0f), 10.0f);
        }
    }
}

// ---------------------------------------------------------------------------
extern "C" void kernel_launch(void* const* d_in, const int* in_sizes, int n_in,
                              void* d_out, int out_size) {
    const float* x  = (const float*)d_in[0];
    const float* Wi = (const float*)d_in[1];
    const float* Wo = (const float*)d_in[2];
    const float* Ci = (const float*)d_in[3];
    const float* Cc = (const float*)d_in[4];
    float* out = (float*)d_out;

    Scratch* s; cudaGetSymbolAddress((void**)&s, g_s);
    float* y1;  cudaGetSymbolAddress((void**)&y1,  g_y1);

    int*  cnt = s->cnt;
    int2* lst = s->lst;
    const int4* lst1 = (const int4*)lst;
    const int4* lst2 = (const int4*)(lst + NSLOTS * LIST_CAP);

    // One memset clears counters AND list padding (zero = src 0, weight 0.0f)
    cudaMemsetAsync(s, 0, sizeof(Scratch));

    compact_kernel<<<4096, 256>>>((const float4*)Ci, (const float4*)Cc,
                                  cnt, lst);

    // Layer 1: fused dispatch(x)+matvec(Wi) -> y1
    mv_kernel<<<GRID_MV, 256>>>(Wi, lst1, (const float4*)x, y1);

    // Layer 2: fused dispatch(y1)+matvec(Wo) -> out
    mv_kernel<<<GRID_MV, 256>>>(Wo, lst2, (const float4*)y1, out);
}

// round 11
// speedup vs baseline: 1.0705x; 1.0705x over previous
#include <cuda_runtime.h>
#include <cuda_bf16.h>
#include <cstdint>

#define CORES   512
#define SLOTS   4
#define SLEN    64
#define PER_CORE (SLOTS * SLEN)          // 256
#define NSLOTS  (CORES * SLOTS)          // 2048 slots per layer
#define VEC_N   (CORES * PER_CORE)       // 131072
#define C_ENTRIES (CORES * SLOTS * CORES * SLOTS)
#define LIST_CAP 4                       // each slot has <=4 sources
#define GRID_MV 592                      // 148 SMs x 4 CTAs (one full wave)
#define MV_TASKS8 (VEC_N / 8)            // 16384 8-row warp tasks
#define GW_STRIDE (GRID_MV * 8)          // 4736 warps

#define CHUNK_F4   2048                  // 32 KB chunk in float4
#define CHUNK_BYTES (CHUNK_F4 * 16)
#define CHUNKS_PER ((C_ENTRIES / 4) / CHUNK_F4)  // 512 per tensor

// Scratch packed so one memset node clears counters + list padding.
struct Scratch {
    int  cnt[2 * NSLOTS];
    int2 lst[2 * NSLOTS * LIST_CAP];     // zero entry = (src 0, weight 0.0f)
};
__device__ Scratch g_s;
__device__ float g_h[VEC_N];
__device__ float g_y1[VEC_N];

// ---------------------------------------------------------------------------
// Bulk-copy compact: each CTA copies one 32 KB chunk of a routing tensor
// into smem via cp.async.bulk (no per-16B LDG issue cost), then scans it
// from smem. C layout [I,J,K,L]: float4 index q = ij*512 + k (vector over l).
// ---------------------------------------------------------------------------
__global__ void __launch_bounds__(256) compact_kernel(
        const float4* __restrict__ C1,
        const float4* __restrict__ C2,
        int* __restrict__ cnt,
        int2* __restrict__ lst) {
    __shared__ alignas(16) float4 buf[CHUNK_F4];
    __shared__ alignas(8) unsigned long long mbar;
    const int tid = threadIdx.x;
    const int chunk = blockIdx.x;
    const bool second = (chunk >= CHUNKS_PER);
    const int c = second ? chunk - CHUNKS_PER : chunk;
    const float4* src = (second ? C2 : C1) + (size_t)c * CHUNK_F4;
    int*  cn = second ? cnt + NSLOTS : cnt;
    int2* ls = second ? lst + NSLOTS * LIST_CAP : lst;
    const int q0 = c * CHUNK_F4;

    const uint32_t mb = (uint32_t)__cvta_generic_to_shared(&mbar);
    const uint32_t sb = (uint32_t)__cvta_generic_to_shared(buf);

    if (tid == 0)
        asm volatile("mbarrier.init.shared.b64 [%0], 1;" :: "r"(mb) : "memory");
    __syncthreads();
    if (tid == 0) {
        asm volatile("mbarrier.arrive.expect_tx.shared.b64 _, [%0], %1;"
                     :: "r"(mb), "r"((uint32_t)CHUNK_BYTES) : "memory");
        asm volatile("cp.async.bulk.shared::cta.global.mbarrier::complete_tx::bytes"
                     " [%0], [%1], %2, [%3];"
                     :: "r"(sb), "l"(src), "r"((uint32_t)CHUNK_BYTES), "r"(mb)
                     : "memory");
    }
    // Wait on phase 0 (acquire orders TMA smem writes before our LDS reads)
    {
        uint32_t done;
        asm volatile(
            "{\n\t.reg .pred p;\n\t"
            "mbarrier.try_wait.parity.acquire.cta.shared::cta.b64 p, [%1], %2;\n\t"
            "selp.b32 %0, 1, 0, p;\n\t}"
            : "=r"(done) : "r"(mb), "r"(0u) : "memory");
        while (!done) {
            asm volatile(
                "{\n\t.reg .pred p;\n\t"
                "mbarrier.try_wait.parity.acquire.cta.shared::cta.b64 p, [%1], %2, 0x989680;\n\t"
                "selp.b32 %0, 1, 0, p;\n\t}"
                : "=r"(done) : "r"(mb), "r"(0u) : "memory");
        }
    }

    // Scan from smem: 8 float4 per thread, conflict-free LDS.128
#pragma unroll
    for (int i = 0; i < 8; i++) {
        const int idx = tid + 256 * i;
        float4 v = buf[idx];
        const int q  = q0 + idx;
        const int ij = q >> 9;
        const int k  = q & 511;
        float vals[4] = {v.x, v.y, v.z, v.w};
#pragma unroll
        for (int l = 0; l < 4; l++) {
            if (vals[l] != 0.0f) {
                int s = k * 4 + l;
                int pos = atomicAdd(&cn[s], 1);
                if (pos < LIST_CAP)
                    ls[s * LIST_CAP + pos] = make_int2(ij, __float_as_int(vals[l]));
            }
        }
    }
}

// ---------------------------------------------------------------------------
// Dispatch gather, count-free: every slot processes exactly 4 (src, w)
// entries; padding entries have w = 0.0f and src = 0 (safe read).
// Thread = (slot s, 4-elem chunk m4). Chain depth 2: list int4 x2 -> src x4.
// ---------------------------------------------------------------------------
__global__ void gather_kernel(const int2* __restrict__ lst,
                              const float4* __restrict__ src4,
                              float4* __restrict__ h4) {
    int idx = blockIdx.x * blockDim.x + threadIdx.x;   // 32768 threads
    int s  = idx >> 4;
    int m4 = idx & 15;
    const int4* lp = reinterpret_cast<const int4*>(lst + s * LIST_CAP);
    int4 e01 = lp[0];   // (src0, w0, src1, w1)
    int4 e23 = lp[1];   // (src2, w2, src3, w3)
    float4 v0 = src4[e01.x * 16 + m4];
    float4 v1 = src4[e01.z * 16 + m4];
    float4 v2 = src4[e23.x * 16 + m4];
    float4 v3 = src4[e23.z * 16 + m4];
    float w0 = __int_as_float(e01.y), w1 = __int_as_float(e01.w);
    float w2 = __int_as_float(e23.y), w3 = __int_as_float(e23.w);
    float4 r;
    r.x = w0 * v0.x + w1 * v1.x + w2 * v2.x + w3 * v3.x;
    r.y = w0 * v0.y + w1 * v1.y + w2 * v2.y + w3 * v3.y;
    r.z = w0 * v0.z + w1 * v1.z + w2 * v2.z + w3 * v3.z;
    r.w = w0 * v0.w + w1 * v1.w + w2 * v2.w + w3 * v3.w;
    h4[idx] = r;
}

// ---------------------------------------------------------------------------
// Barrier-free streaming matvec + capped ReLU, 8-row warp tasks (R9 version).
// W per-core layout [j,k,l,m]: row r=(j,l) stride j:16384 l:64; col c=(k,m).
// ---------------------------------------------------------------------------
__global__ void __launch_bounds__(256, 4) mv_kernel(
        const float* __restrict__ W,
        const float* __restrict__ h,
        float* __restrict__ y) {
    const int warp = threadIdx.x >> 5, lane = threadIdx.x & 31;
    const int lg  = lane & 7;
    const int sub = lane >> 3;
    const int gw  = blockIdx.x * 8 + warp;

    for (int t = gw; t < MV_TASKS8; t += GW_STRIDE) {
        const int core = t >> 5;
        const int rg   = t & 31;
        const int r0 = (rg << 3) + sub;       // rows r0 and r0+4
        const int r1 = r0 + 4;
        const float* hb = h + (core << 8);

        float4 hv[8];
#pragma unroll
        for (int tt = 0; tt < 8; tt++)
            hv[tt] = *reinterpret_cast<const float4*>(hb + 4 * lg + 32 * tt);

        const float* Wc = W + ((size_t)core << 16);
        const float* rb0 = Wc + ((r0 >> 6) << 14) + ((r0 & 63) << 6);
        const float* rb1 = Wc + ((r1 >> 6) << 14) + ((r1 & 63) << 6);

        float a0 = 0.f, a1 = 0.f;
#pragma unroll
        for (int tt = 0; tt < 8; tt++) {
            const int c = 4 * lg + 32 * tt;
            const int off = ((c >> 6) << 12) + (c & 63);
            float4 w0 = __ldcs(reinterpret_cast<const float4*>(rb0 + off));
            float4 w1 = __ldcs(reinterpret_cast<const float4*>(rb1 + off));
            a0 += w0.x * hv[tt].x + w0.y * hv[tt].y + w0.z * hv[tt].z + w0.w * hv[tt].w;
            a1 += w1.x * hv[tt].x + w1.y * hv[tt].y + w1.z * hv[tt].z + w1.w * hv[tt].w;
        }
        a0 += __shfl_xor_sync(0xffffffffu, a0, 1);
        a1 += __shfl_xor_sync(0xffffffffu, a1, 1);
        a0 += __shfl_xor_sync(0xffffffffu, a0, 2);
        a1 += __shfl_xor_sync(0xffffffffu, a1, 2);
        a0 += __shfl_xor_sync(0xffffffffu, a0, 4);
        a1 += __shfl_xor_sync(0xffffffffu, a1, 4);
        if (lg == 0) {
            y[(core << 8) + r0] = fminf(fmaxf(a0, 0.0f), 10.0f);
            y[(core << 8) + r1] = fminf(fmaxf(a1, 0.0f), 10.0f);
        }
    }
}

// ---------------------------------------------------------------------------
extern "C" void kernel_launch(void* const* d_in, const int* in_sizes, int n_in,
                              void* d_out, int out_size) {
    const float* x  = (const float*)d_in[0];
    const float* Wi = (const float*)d_in[1];
    const float* Wo = (const float*)d_in[2];
    const float* Ci = (const float*)d_in[3];
    const float* Cc = (const float*)d_in[4];
    float* out = (float*)d_out;

    Scratch* s; cudaGetSymbolAddress((void**)&s, g_s);
    float* h;   cudaGetSymbolAddress((void**)&h,   g_h);
    float* y1;  cudaGetSymbolAddress((void**)&y1,  g_y1);

    int*  cnt = s->cnt;
    int2* lst = s->lst;

    // One memset clears counters AND list padding (zero = src 0, weight 0.0f)
    cudaMemsetAsync(s, 0, sizeof(Scratch));

    compact_kernel<<<2 * CHUNKS_PER, 256>>>((const float4*)Ci, (const float4*)Cc,
                                            cnt, lst);

    // Layer 1
    gather_kernel<<<256, 128>>>(lst, (const float4*)x, (float4*)h);
    mv_kernel<<<GRID_MV, 256>>>(Wi, h, y1);

    // Layer 2
    gather_kernel<<<256, 128>>>(lst + NSLOTS * LIST_CAP,
                                (const float4*)y1, (float4*)h);
    mv_kernel<<<GRID_MV, 256>>>(Wo, h, out);
}

// round 12
// speedup vs baseline: 1.1115x; 1.0383x over previous
#include <cuda_runtime.h>
#include <cuda_bf16.h>
#include <cstdint>

#define CORES   512
#define SLOTS   4
#define SLEN    64
#define PER_CORE (SLOTS * SLEN)          // 256
#define NSLOTS  (CORES * SLOTS)          // 2048 slots per layer
#define VEC_N   (CORES * PER_CORE)       // 131072
#define C_ENTRIES (CORES * SLOTS * CORES * SLOTS)
#define LIST_CAP 4                       // each slot has <=4 sources
#define GRID_MV 592                      // 148 SMs x 4 CTAs (one full wave)
#define MV_TASKS8 (VEC_N / 8)            // 16384 8-row warp tasks
#define GW_STRIDE (GRID_MV * 8)          // 4736 warps

#define CHUNK_F4   2048                  // 32 KB chunk in float4
#define CHUNK_BYTES (CHUNK_F4 * 16)
#define CHUNKS_PER ((C_ENTRIES / 4) / CHUNK_F4)  // 512 per tensor

// Scratch packed so one memset node clears counters + list padding.
struct Scratch {
    int  cnt[2 * NSLOTS];
    int2 lst[2 * NSLOTS * LIST_CAP];     // zero entry = (src 0, weight 0.0f)
};
__device__ Scratch g_s;
__device__ float g_h[VEC_N];
__device__ float g_y1[VEC_N];

// ---------------------------------------------------------------------------
// Bulk-copy compact: each CTA copies one 32 KB chunk of a routing tensor
// into smem via cp.async.bulk, then scans it from smem.
// C layout [I,J,K,L]: float4 index q = ij*512 + k (vector over l).
// ---------------------------------------------------------------------------
__global__ void __launch_bounds__(256) compact_kernel(
        const float4* __restrict__ C1,
        const float4* __restrict__ C2,
        int* __restrict__ cnt,
        int2* __restrict__ lst) {
    __shared__ alignas(16) float4 buf[CHUNK_F4];
    __shared__ alignas(8) unsigned long long mbar;
    const int tid = threadIdx.x;
    const int chunk = blockIdx.x;
    const bool second = (chunk >= CHUNKS_PER);
    const int c = second ? chunk - CHUNKS_PER : chunk;
    const float4* src = (second ? C2 : C1) + (size_t)c * CHUNK_F4;
    int*  cn = second ? cnt + NSLOTS : cnt;
    int2* ls = second ? lst + NSLOTS * LIST_CAP : lst;
    const int q0 = c * CHUNK_F4;

    const uint32_t mb = (uint32_t)__cvta_generic_to_shared(&mbar);
    const uint32_t sb = (uint32_t)__cvta_generic_to_shared(buf);

    if (tid == 0)
        asm volatile("mbarrier.init.shared.b64 [%0], 1;" :: "r"(mb) : "memory");
    __syncthreads();
    if (tid == 0) {
        asm volatile("mbarrier.arrive.expect_tx.shared.b64 _, [%0], %1;"
                     :: "r"(mb), "r"((uint32_t)CHUNK_BYTES) : "memory");
        asm volatile("cp.async.bulk.shared::cta.global.mbarrier::complete_tx::bytes"
                     " [%0], [%1], %2, [%3];"
                     :: "r"(sb), "l"(src), "r"((uint32_t)CHUNK_BYTES), "r"(mb)
                     : "memory");
    }
    {
        uint32_t done;
        asm volatile(
            "{\n\t.reg .pred p;\n\t"
            "mbarrier.try_wait.parity.acquire.cta.shared::cta.b64 p, [%1], %2;\n\t"
            "selp.b32 %0, 1, 0, p;\n\t}"
            : "=r"(done) : "r"(mb), "r"(0u) : "memory");
        while (!done) {
            asm volatile(
                "{\n\t.reg .pred p;\n\t"
                "mbarrier.try_wait.parity.acquire.cta.shared::cta.b64 p, [%1], %2, 0x989680;\n\t"
                "selp.b32 %0, 1, 0, p;\n\t}"
                : "=r"(done) : "r"(mb), "r"(0u) : "memory");
        }
    }

#pragma unroll
    for (int i = 0; i < 8; i++) {
        const int idx = tid + 256 * i;
        float4 v = buf[idx];
        const int q  = q0 + idx;
        const int ij = q >> 9;
        const int k  = q & 511;
        float vals[4] = {v.x, v.y, v.z, v.w};
#pragma unroll
        for (int l = 0; l < 4; l++) {
            if (vals[l] != 0.0f) {
                int s = k * 4 + l;
                int pos = atomicAdd(&cn[s], 1);
                if (pos < LIST_CAP)
                    ls[s * LIST_CAP + pos] = make_int2(ij, __float_as_int(vals[l]));
            }
        }
    }
    cudaTriggerProgrammaticLaunchCompletion();
}

// ---------------------------------------------------------------------------
// Dispatch gather, count-free (4 fixed entries per slot; padding w=0/src=0).
// PDL consumer (lst or y1) + producer (h).
// ---------------------------------------------------------------------------
__global__ void gather_kernel(const int2* __restrict__ lst,
                              const float4* __restrict__ src4,
                              float4* __restrict__ h4) {
    int idx = blockIdx.x * blockDim.x + threadIdx.x;   // 32768 threads
    int s  = idx >> 4;
    int m4 = idx & 15;
    cudaGridDependencySynchronize();     // wait: compact lists / y1 visible
    const int4* lp = reinterpret_cast<const int4*>(lst + s * LIST_CAP);
    int4 e01 = lp[0];   // (src0, w0, src1, w1)
    int4 e23 = lp[1];   // (src2, w2, src3, w3)
    float4 v0 = src4[e01.x * 16 + m4];
    float4 v1 = src4[e01.z * 16 + m4];
    float4 v2 = src4[e23.x * 16 + m4];
    float4 v3 = src4[e23.z * 16 + m4];
    float w0 = __int_as_float(e01.y), w1 = __int_as_float(e01.w);
    float w2 = __int_as_float(e23.y), w3 = __int_as_float(e23.w);
    float4 r;
    r.x = w0 * v0.x + w1 * v1.x + w2 * v2.x + w3 * v3.x;
    r.y = w0 * v0.y + w1 * v1.y + w2 * v2.y + w3 * v3.y;
    r.z = w0 * v0.z + w1 * v1.z + w2 * v2.z + w3 * v3.z;
    r.w = w0 * v0.w + w1 * v1.w + w2 * v2.w + w3 * v3.w;
    h4[idx] = r;
    cudaTriggerProgrammaticLaunchCompletion();
}

// ---------------------------------------------------------------------------
// Barrier-free streaming matvec + capped ReLU, 8-row warp tasks.
// PDL consumer (h) + producer (y1).
// W per-core layout [j,k,l,m]: row r=(j,l) stride j:16384 l:64; col c=(k,m).
// ---------------------------------------------------------------------------
__global__ void __launch_bounds__(256, 4) mv_kernel(
        const float* __restrict__ W,
        const float* __restrict__ h,
        float* __restrict__ y) {
    const int warp = threadIdx.x >> 5, lane = threadIdx.x & 31;
    const int lg  = lane & 7;
    const int sub = lane >> 3;
    const int gw  = blockIdx.x * 8 + warp;

    cudaGridDependencySynchronize();     // wait: h from gather visible

    for (int t = gw; t < MV_TASKS8; t += GW_STRIDE) {
        const int core = t >> 5;
        const int rg   = t & 31;
        const int r0 = (rg << 3) + sub;       // rows r0 and r0+4
        const int r1 = r0 + 4;
        const float* hb = h + (core << 8);

        float4 hv[8];
#pragma unroll
        for (int tt = 0; tt < 8; tt++)
            hv[tt] = *reinterpret_cast<const float4*>(hb + 4 * lg + 32 * tt);

        const float* Wc = W + ((size_t)core << 16);
        const float* rb0 = Wc + ((r0 >> 6) << 14) + ((r0 & 63) << 6);
        const float* rb1 = Wc + ((r1 >> 6) << 14) + ((r1 & 63) << 6);

        float a0 = 0.f, a1 = 0.f;
#pragma unroll
        for (int tt = 0; tt < 8; tt++) {
            const int c = 4 * lg + 32 * tt;
            const int off = ((c >> 6) << 12) + (c & 63);
            float4 w0 = __ldcs(reinterpret_cast<const float4*>(rb0 + off));
            float4 w1 = __ldcs(reinterpret_cast<const float4*>(rb1 + off));
            a0 += w0.x * hv[tt].x + w0.y * hv[tt].y + w0.z * hv[tt].z + w0.w * hv[tt].w;
            a1 += w1.x * hv[tt].x + w1.y * hv[tt].y + w1.z * hv[tt].z + w1.w * hv[tt].w;
        }
        a0 += __shfl_xor_sync(0xffffffffu, a0, 1);
        a1 += __shfl_xor_sync(0xffffffffu, a1, 1);
        a0 += __shfl_xor_sync(0xffffffffu, a0, 2);
        a1 += __shfl_xor_sync(0xffffffffu, a1, 2);
        a0 += __shfl_xor_sync(0xffffffffu, a0, 4);
        a1 += __shfl_xor_sync(0xffffffffu, a1, 4);
        if (lg == 0) {
            y[(core << 8) + r0] = fminf(fmaxf(a0, 0.0f), 10.0f);
            y[(core << 8) + r1] = fminf(fmaxf(a1, 0.0f), 10.0f);
        }
    }
    cudaTriggerProgrammaticLaunchCompletion();
}

// ---------------------------------------------------------------------------
// PDL launch helpers
// ---------------------------------------------------------------------------
template <typename... Args>
static void launch_pdl(void (*kern)(Args...), dim3 grid, dim3 block,
                       Args... args) {
    cudaLaunchConfig_t cfg = {};
    cfg.gridDim = grid;
    cfg.blockDim = block;
    cfg.dynamicSmemBytes = 0;
    cfg.stream = 0;
    cudaLaunchAttribute at[1];
    at[0].id = cudaLaunchAttributeProgrammaticStreamSerialization;
    at[0].val.programmaticStreamSerializationAllowed = 1;
    cfg.attrs = at;
    cfg.numAttrs = 1;
    cudaLaunchKernelEx(&cfg, kern, args...);
}

extern "C" void kernel_launch(void* const* d_in, const int* in_sizes, int n_in,
                              void* d_out, int out_size) {
    const float* x  = (const float*)d_in[0];
    const float* Wi = (const float*)d_in[1];
    const float* Wo = (const float*)d_in[2];
    const float* Ci = (const float*)d_in[3];
    const float* Cc = (const float*)d_in[4];
    float* out = (float*)d_out;

    Scratch* s; cudaGetSymbolAddress((void**)&s, g_s);
    float* h;   cudaGetSymbolAddress((void**)&h,   g_h);
    float* y1;  cudaGetSymbolAddress((void**)&y1,  g_y1);

    int*  cnt = s->cnt;
    int2* lst = s->lst;

    // One memset clears counters AND list padding (zero = src 0, weight 0.0f)
    cudaMemsetAsync(s, 0, sizeof(Scratch));

    // compact launched normally (its upstream is a memset node)
    compact_kernel<<<2 * CHUNKS_PER, 256>>>((const float4*)Ci, (const float4*)Cc,
                                            cnt, lst);

    // Layer 1 (PDL edges: compact->gather1->mv1)
    launch_pdl(gather_kernel, dim3(256), dim3(128),
               (const int2*)lst, (const float4*)x, (float4*)h);
    launch_pdl(mv_kernel, dim3(GRID_MV), dim3(256),
               (const float*)Wi, (const float*)h, (float*)y1);

    // Layer 2 (PDL edges: mv1->gather2->mv2)
    launch_pdl(gather_kernel, dim3(256), dim3(128),
               (const int2*)(lst + NSLOTS * LIST_CAP), (const float4*)y1,
               (float4*)h);
    launch_pdl(mv_kernel, dim3(GRID_MV), dim3(256),
               (const float*)Wo, (const float*)h, (float*)out);
}

// round 13
// speedup vs baseline: 1.1592x; 1.0429x over previous
#include <cuda_runtime.h>
#include <cuda_bf16.h>
#include <cstdint>

#define CORES   512
#define SLOTS   4
#define SLEN    64
#define PER_CORE (SLOTS * SLEN)          // 256
#define NSLOTS  (CORES * SLOTS)          // 2048 slots per layer
#define VEC_N   (CORES * PER_CORE)       // 131072
#define C_ENTRIES (CORES * SLOTS * CORES * SLOTS)
#define LIST_CAP 4                       // each slot has <=4 sources
#define GRID_MV 592                      // 148 SMs x 4 CTAs (one full wave)
#define MV_TASKS8 (VEC_N / 8)            // 16384 8-row warp tasks
#define GW_STRIDE (GRID_MV * 8)          // 4736 warps

#define CHUNK_F4   2048                  // 32 KB chunk in float4
#define CHUNK_BYTES (CHUNK_F4 * 16)
#define CHUNKS_PER ((C_ENTRIES / 4) / CHUNK_F4)  // 512 per tensor

// Scratch packed so one memset node clears counters + list padding.
struct Scratch {
    int  cnt[2 * NSLOTS];
    int2 lst[2 * NSLOTS * LIST_CAP];     // zero entry = (src 0, weight 0.0f)
};
__device__ Scratch g_s;
__device__ float g_h[VEC_N];
__device__ float g_y1[VEC_N];

// ---------------------------------------------------------------------------
// Bulk-copy compact: each CTA copies one 32 KB chunk of a routing tensor
// into smem via cp.async.bulk, then scans it from smem.
// C layout [I,J,K,L]: float4 index q = ij*512 + k (vector over l).
// ---------------------------------------------------------------------------
__global__ void __launch_bounds__(256) compact_kernel(
        const float4* __restrict__ C1,
        const float4* __restrict__ C2,
        int* __restrict__ cnt,
        int2* __restrict__ lst) {
    __shared__ alignas(16) float4 buf[CHUNK_F4];
    __shared__ alignas(8) unsigned long long mbar;
    const int tid = threadIdx.x;
    const int chunk = blockIdx.x;
    const bool second = (chunk >= CHUNKS_PER);
    const int c = second ? chunk - CHUNKS_PER : chunk;
    const float4* src = (second ? C2 : C1) + (size_t)c * CHUNK_F4;
    int*  cn = second ? cnt + NSLOTS : cnt;
    int2* ls = second ? lst + NSLOTS * LIST_CAP : lst;
    const int q0 = c * CHUNK_F4;

    const uint32_t mb = (uint32_t)__cvta_generic_to_shared(&mbar);
    const uint32_t sb = (uint32_t)__cvta_generic_to_shared(buf);

    if (tid == 0)
        asm volatile("mbarrier.init.shared.b64 [%0], 1;" :: "r"(mb) : "memory");
    __syncthreads();
    if (tid == 0) {
        asm volatile("mbarrier.arrive.expect_tx.shared.b64 _, [%0], %1;"
                     :: "r"(mb), "r"((uint32_t)CHUNK_BYTES) : "memory");
        asm volatile("cp.async.bulk.shared::cta.global.mbarrier::complete_tx::bytes"
                     " [%0], [%1], %2, [%3];"
                     :: "r"(sb), "l"(src), "r"((uint32_t)CHUNK_BYTES), "r"(mb)
                     : "memory");
    }
    {
        uint32_t done;
        asm volatile(
            "{\n\t.reg .pred p;\n\t"
            "mbarrier.try_wait.parity.acquire.cta.shared::cta.b64 p, [%1], %2;\n\t"
            "selp.b32 %0, 1, 0, p;\n\t}"
            : "=r"(done) : "r"(mb), "r"(0u) : "memory");
        while (!done) {
            asm volatile(
                "{\n\t.reg .pred p;\n\t"
                "mbarrier.try_wait.parity.acquire.cta.shared::cta.b64 p, [%1], %2, 0x989680;\n\t"
                "selp.b32 %0, 1, 0, p;\n\t}"
                : "=r"(done) : "r"(mb), "r"(0u) : "memory");
        }
    }

#pragma unroll
    for (int i = 0; i < 8; i++) {
        const int idx = tid + 256 * i;
        float4 v = buf[idx];
        const int q  = q0 + idx;
        const int ij = q >> 9;
        const int k  = q & 511;
        float vals[4] = {v.x, v.y, v.z, v.w};
#pragma unroll
        for (int l = 0; l < 4; l++) {
            if (vals[l] != 0.0f) {
                int s = k * 4 + l;
                int pos = atomicAdd(&cn[s], 1);
                if (pos < LIST_CAP)
                    ls[s * LIST_CAP + pos] = make_int2(ij, __float_as_int(vals[l]));
            }
        }
    }
    cudaTriggerProgrammaticLaunchCompletion();
}

// ---------------------------------------------------------------------------
// Dispatch gather, count-free (4 fixed entries per slot; padding w=0/src=0).
// ---------------------------------------------------------------------------
__global__ void gather_kernel(const int2* __restrict__ lst,
                              const float4* __restrict__ src4,
                              float4* __restrict__ h4) {
    int idx = blockIdx.x * blockDim.x + threadIdx.x;   // 32768 threads
    int s  = idx >> 4;
    int m4 = idx & 15;
    cudaGridDependencySynchronize();     // wait: compact lists / y1 visible
    const int4* lp = reinterpret_cast<const int4*>(lst + s * LIST_CAP);
    int4 e01 = lp[0];   // (src0, w0, src1, w1)
    int4 e23 = lp[1];   // (src2, w2, src3, w3)
    float4 v0 = src4[e01.x * 16 + m4];
    float4 v1 = src4[e01.z * 16 + m4];
    float4 v2 = src4[e23.x * 16 + m4];
    float4 v3 = src4[e23.z * 16 + m4];
    float w0 = __int_as_float(e01.y), w1 = __int_as_float(e01.w);
    float w2 = __int_as_float(e23.y), w3 = __int_as_float(e23.w);
    float4 r;
    r.x = w0 * v0.x + w1 * v1.x + w2 * v2.x + w3 * v3.x;
    r.y = w0 * v0.y + w1 * v1.y + w2 * v2.y + w3 * v3.y;
    r.z = w0 * v0.z + w1 * v1.z + w2 * v2.z + w3 * v3.z;
    r.w = w0 * v0.w + w1 * v1.w + w2 * v2.w + w3 * v3.w;
    h4[idx] = r;
    cudaTriggerProgrammaticLaunchCompletion();
}

// ---------------------------------------------------------------------------
// Barrier-free streaming matvec + capped ReLU, 8-row warp tasks, with
// pre-sync L2 prefetch of the first task's W footprint (W is h-independent,
// so DRAM streams during the upstream gather instead of idling).
// Task footprint: j = rg>>3 fixed, 8 consecutive l -> 4 chunks of 2KB
// (one per k-block, spaced 16KB). 64 x 128B lines, 2 prefetches per lane.
// W per-core layout [j,k,l,m]: row r=(j,l) stride j:16384 l:64; col c=(k,m).
// ---------------------------------------------------------------------------
__global__ void __launch_bounds__(256, 4) mv_kernel(
        const float* __restrict__ W,
        const float* __restrict__ h,
        float* __restrict__ y) {
    const int warp = threadIdx.x >> 5, lane = threadIdx.x & 31;
    const int lg  = lane & 7;
    const int sub = lane >> 3;
    const int gw  = blockIdx.x * 8 + warp;

    // --- pre-sync: prefetch first task's W (8KB) into L2 ---
    if (gw < MV_TASKS8) {
        const int core = gw >> 5;
        const int rg   = gw & 31;
        const int j  = rg >> 3;
        const int l0 = (rg << 3) & 63;
        const float* tb = W + ((size_t)core << 16) + (j << 14) + (l0 << 6);
#pragma unroll
        for (int p = 0; p < 2; p++) {
            const int line  = lane + 32 * p;     // 0..63
            const int chunk = line >> 4;         // k-block 0..3
            const int off   = line & 15;         // 128B line within 2KB
            const float* pa = tb + (chunk << 12) + (off << 5);
            asm volatile("prefetch.global.L2 [%0];" :: "l"(pa));
        }
    }

    cudaGridDependencySynchronize();     // wait: h from gather visible

    for (int t = gw; t < MV_TASKS8; t += GW_STRIDE) {
        const int core = t >> 5;
        const int rg   = t & 31;
        const int r0 = (rg << 3) + sub;       // rows r0 and r0+4
        const int r1 = r0 + 4;
        const float* hb = h + (core << 8);

        float4 hv[8];
#pragma unroll
        for (int tt = 0; tt < 8; tt++)
            hv[tt] = *reinterpret_cast<const float4*>(hb + 4 * lg + 32 * tt);

        const float* Wc = W + ((size_t)core << 16);
        const float* rb0 = Wc + ((r0 >> 6) << 14) + ((r0 & 63) << 6);
        const float* rb1 = Wc + ((r1 >> 6) << 14) + ((r1 & 63) << 6);

        float a0 = 0.f, a1 = 0.f;
#pragma unroll
        for (int tt = 0; tt < 8; tt++) {
            const int c = 4 * lg + 32 * tt;
            const int off = ((c >> 6) << 12) + (c & 63);
            float4 w0 = __ldcs(reinterpret_cast<const float4*>(rb0 + off));
            float4 w1 = __ldcs(reinterpret_cast<const float4*>(rb1 + off));
            a0 += w0.x * hv[tt].x + w0.y * hv[tt].y + w0.z * hv[tt].z + w0.w * hv[tt].w;
            a1 += w1.x * hv[tt].x + w1.y * hv[tt].y + w1.z * hv[tt].z + w1.w * hv[tt].w;
        }
        a0 += __shfl_xor_sync(0xffffffffu, a0, 1);
        a1 += __shfl_xor_sync(0xffffffffu, a1, 1);
        a0 += __shfl_xor_sync(0xffffffffu, a0, 2);
        a1 += __shfl_xor_sync(0xffffffffu, a1, 2);
        a0 += __shfl_xor_sync(0xffffffffu, a0, 4);
        a1 += __shfl_xor_sync(0xffffffffu, a1, 4);
        if (lg == 0) {
            y[(core << 8) + r0] = fminf(fmaxf(a0, 0.0f), 10.0f);
            y[(core << 8) + r1] = fminf(fmaxf(a1, 0.0f), 10.0f);
        }
    }
    cudaTriggerProgrammaticLaunchCompletion();
}

// ---------------------------------------------------------------------------
// PDL launch helper
// ---------------------------------------------------------------------------
template <typename... Args>
static void launch_pdl(void (*kern)(Args...), dim3 grid, dim3 block,
                       Args... args) {
    cudaLaunchConfig_t cfg = {};
    cfg.gridDim = grid;
    cfg.blockDim = block;
    cfg.dynamicSmemBytes = 0;
    cfg.stream = 0;
    cudaLaunchAttribute at[1];
    at[0].id = cudaLaunchAttributeProgrammaticStreamSerialization;
    at[0].val.programmaticStreamSerializationAllowed = 1;
    cfg.attrs = at;
    cfg.numAttrs = 1;
    cudaLaunchKernelEx(&cfg, kern, args...);
}

extern "C" void kernel_launch(void* const* d_in, const int* in_sizes, int n_in,
                              void* d_out, int out_size) {
    const float* x  = (const float*)d_in[0];
    const float* Wi = (const float*)d_in[1];
    const float* Wo = (const float*)d_in[2];
    const float* Ci = (const float*)d_in[3];
    const float* Cc = (const float*)d_in[4];
    float* out = (float*)d_out;

    Scratch* s; cudaGetSymbolAddress((void**)&s, g_s);
    float* h;   cudaGetSymbolAddress((void**)&h,   g_h);
    float* y1;  cudaGetSymbolAddress((void**)&y1,  g_y1);

    int*  cnt = s->cnt;
    int2* lst = s->lst;

    // One memset clears counters AND list padding (zero = src 0, weight 0.0f)
    cudaMemsetAsync(s, 0, sizeof(Scratch));

    compact_kernel<<<2 * CHUNKS_PER, 256>>>((const float4*)Ci, (const float4*)Cc,
                                            cnt, lst);

    // Layer 1 (PDL edges: compact->gather1->mv1)
    launch_pdl(gather_kernel, dim3(256), dim3(128),
               (const int2*)lst, (const float4*)x, (float4*)h);
    launch_pdl(mv_kernel, dim3(GRID_MV), dim3(256),
               (const float*)Wi, (const float*)h, (float*)y1);

    // Layer 2 (PDL edges: mv1->gather2->mv2)
    launch_pdl(gather_kernel, dim3(256), dim3(128),
               (const int2*)(lst + NSLOTS * LIST_CAP), (const float4*)y1,
               (float4*)h);
    launch_pdl(mv_kernel, dim3(GRID_MV), dim3(256),
               (const float*)Wo, (const float*)h, (float*)out);
}